// round 12
// baseline (speedup 1.0000x reference)
#include <cuda_runtime.h>
#include <cuda_bf16.h>

// Parameter block layout (548 floats):
//  [0   .. 256)  Ur1[k*16+j]   (U1 real, row-major: y_k = sum_j U1[k][j] x_j)
//  [256 .. 512)  Ui1[k*16+j]
//  [512 .. 528)  Ur2[k*4+j]
//  [528 .. 544)  Ui2[k*4+j]
//  [544] W0  [545] W1  [546] b0  [547] b1
__device__ float g_params[548];
__constant__ float c_p[548];

// ---------------------------------------------------------------------------
// Setup kernel: build U1 (16x16) and U2 (4x4) from circuit parameters.
// Single block of 256 threads. Runs once per launch (graph replay safe,
// deterministic).
// ---------------------------------------------------------------------------
__global__ void setup_kernel(const float* __restrict__ f1,
                             const float* __restrict__ p1,
                             const float* __restrict__ f2,
                             const float* __restrict__ p2,
                             const float* __restrict__ W,
                             const float* __restrict__ b) {
    __shared__ float2 U[256];
    __shared__ float2 T[256];
    const float TWO_PI = 6.2831853071795864769f;

    const int t = threadIdx.x;
    const int m = t >> 4;     // row (state index)
    const int j = t & 15;     // col

    // ---- 1. U = Q (QFT on 4 qubits): Q[m][j] = exp(2*pi*i*m*j/16)/4 ----
    {
        int mj = (m * j) & 15;
        float s, c;
        sincosf(TWO_PI * (float)mj * (1.0f / 16.0f), &s, &c);
        U[t] = make_float2(c * 0.25f, s * 0.25f);
    }
    __syncthreads();

    // ---- 2. RZ(f1[i]) on each wire i: diagonal, row phase ----
    {
        float ph = 0.0f;
        #pragma unroll
        for (int i = 0; i < 4; ++i) {
            float half = 0.5f * f1[i];
            ph += ((m >> (3 - i)) & 1) ? half : -half;   // e^{-it/2} if bit=0 else e^{+it/2}
        }
        float s, c; sincosf(ph, &s, &c);
        float2 v = U[t];
        U[t] = make_float2(v.x * c - v.y * s, v.x * s + v.y * c);
    }
    __syncthreads();

    // ---- 3. U = Qdag @ U : T[m][j] = (1/4) sum_k exp(-2*pi*i*k*m/16) U[k][j] ----
    {
        float2 acc = make_float2(0.f, 0.f);
        for (int k = 0; k < 16; ++k) {
            int km = (k * m) & 15;
            float s, c;
            sincosf(-TWO_PI * (float)km * (1.0f / 16.0f), &s, &c);
            float2 v = U[k * 16 + j];
            acc.x += c * v.x - s * v.y;
            acc.y += c * v.y + s * v.x;
        }
        T[t] = make_float2(acc.x * 0.25f, acc.y * 0.25f);
    }
    __syncthreads();
    U[t] = T[t];
    __syncthreads();

    // Gate helpers (all threads execute; syncs are uniform).
    auto crz = [&](float theta, int cm, int tm) {
        if (m & cm) {
            float ph = (m & tm) ? 0.5f * theta : -0.5f * theta;
            float s, c; sincosf(ph, &s, &c);
            float2 v = U[t];
            U[t] = make_float2(v.x * c - v.y * s, v.x * s + v.y * c);
        }
        __syncthreads();
    };
    auto xgate = [&](int fm) {
        float2 v = U[(m ^ fm) * 16 + j];
        __syncthreads();
        U[t] = v;
        __syncthreads();
    };
    auto crx = [&](float theta, int cm, int tm) {
        float s, c; sincosf(0.5f * theta, &s, &c);
        float2 vs = U[t];
        float2 vp = U[(m ^ tm) * 16 + j];
        __syncthreads();
        if (m & cm) {
            // new = c*vs + (-i*s)*vp  ->  re = c*vs.re + s*vp.im ; im = c*vs.im - s*vp.re
            U[t] = make_float2(c * vs.x + s * vp.y, c * vs.y - s * vp.x);
        }
        __syncthreads();
    };

    // wire0: control bit mask 8, target mask 4. wire2: control mask 2, target mask 1.
    crz(p1[0], 8, 4); xgate(8); crx(p1[1], 8, 4); xgate(8);
    crz(p1[0], 2, 1); xgate(2); crx(p1[1], 2, 1); xgate(2);

    g_params[t]       = U[t].x;
    g_params[256 + t] = U[t].y;

    // ---- U2 (4x4), serial on thread 0 ----
    if (t == 0) {
        float2 V[16], Tm[16];
        // Q (QFT on 2 qubits)
        for (int mm = 0; mm < 4; ++mm)
            for (int jj = 0; jj < 4; ++jj) {
                int mj = (mm * jj) & 3;
                float s, c; sincosf(TWO_PI * (float)mj * 0.25f, &s, &c);
                V[mm * 4 + jj] = make_float2(c * 0.5f, s * 0.5f);
            }
        // RZ(f2[0]) wire0 (mask 2), RZ(f2[1]) wire1 (mask 1): diagonal
        for (int mm = 0; mm < 4; ++mm) {
            float ph = ((mm & 2) ? 0.5f : -0.5f) * f2[0]
                     + ((mm & 1) ? 0.5f : -0.5f) * f2[1];
            float s, c; sincosf(ph, &s, &c);
            for (int jj = 0; jj < 4; ++jj) {
                float2 v = V[mm * 4 + jj];
                V[mm * 4 + jj] = make_float2(v.x * c - v.y * s, v.x * s + v.y * c);
            }
        }
        // Qdag @ V
        for (int mm = 0; mm < 4; ++mm)
            for (int jj = 0; jj < 4; ++jj) {
                float2 acc = make_float2(0.f, 0.f);
                for (int k = 0; k < 4; ++k) {
                    int km = (k * mm) & 3;
                    float s, c; sincosf(-TWO_PI * (float)km * 0.25f, &s, &c);
                    float2 v = V[k * 4 + jj];
                    acc.x += c * v.x - s * v.y;
                    acc.y += c * v.y + s * v.x;
                }
                Tm[mm * 4 + jj] = make_float2(acc.x * 0.5f, acc.y * 0.5f);
            }
        for (int q = 0; q < 16; ++q) V[q] = Tm[q];
        // CRZ(p2[0]) wire0: control mask 2, target mask 1
        for (int mm = 0; mm < 4; ++mm) {
            if (mm & 2) {
                float ph = (mm & 1) ? 0.5f * p2[0] : -0.5f * p2[0];
                float s, c; sincosf(ph, &s, &c);
                for (int jj = 0; jj < 4; ++jj) {
                    float2 v = V[mm * 4 + jj];
                    V[mm * 4 + jj] = make_float2(v.x * c - v.y * s, v.x * s + v.y * c);
                }
            }
        }
        // X wire0: swap rows m <-> m^2
        for (int jj = 0; jj < 4; ++jj) {
            float2 tmp = V[0 * 4 + jj]; V[0 * 4 + jj] = V[2 * 4 + jj]; V[2 * 4 + jj] = tmp;
            tmp = V[1 * 4 + jj]; V[1 * 4 + jj] = V[3 * 4 + jj]; V[3 * 4 + jj] = tmp;
        }
        // CRX(p2[1]) wire0: rows 2,3 mix
        {
            float s, c; sincosf(0.5f * p2[1], &s, &c);
            for (int jj = 0; jj < 4; ++jj) {
                float2 r2 = V[2 * 4 + jj], r3 = V[3 * 4 + jj];
                V[2 * 4 + jj] = make_float2(c * r2.x + s * r3.y, c * r2.y - s * r3.x);
                V[3 * 4 + jj] = make_float2(c * r3.x + s * r2.y, c * r3.y - s * r2.x);
            }
        }
        // X wire0 again
        for (int jj = 0; jj < 4; ++jj) {
            float2 tmp = V[0 * 4 + jj]; V[0 * 4 + jj] = V[2 * 4 + jj]; V[2 * 4 + jj] = tmp;
            tmp = V[1 * 4 + jj]; V[1 * 4 + jj] = V[3 * 4 + jj]; V[3 * 4 + jj] = tmp;
        }
        for (int q = 0; q < 16; ++q) {
            g_params[512 + q] = V[q].x;
            g_params[528 + q] = V[q].y;
        }
        g_params[544] = W[0];
        g_params[545] = W[1];
        g_params[546] = b[0];
        g_params[547] = b[1];
    }
}

// ---------------------------------------------------------------------------
// Main kernel: one batch element per thread. Coefficients come from constant
// memory -> warp-uniform LDCU feeding FFMA (no per-lane memory traffic).
// ---------------------------------------------------------------------------
__global__ void __launch_bounds__(256)
qfcn_main(const float4* __restrict__ x, float2* __restrict__ out, int B) {
    int i = blockIdx.x * blockDim.x + threadIdx.x;
    if (i >= B) return;

    float4 a0 = x[4 * i + 0];
    float4 a1 = x[4 * i + 1];
    float4 a2 = x[4 * i + 2];
    float4 a3 = x[4 * i + 3];
    float xv[16] = {a0.x, a0.y, a0.z, a0.w,
                    a1.x, a1.y, a1.z, a1.w,
                    a2.x, a2.y, a2.z, a2.w,
                    a3.x, a3.y, a3.z, a3.w};

    float n2 = 0.f;
    #pragma unroll
    for (int j = 0; j < 16; ++j) n2 = fmaf(xv[j], xv[j], n2);

    // y = U1 @ x   (x real): 512 FFMA
    float yr[16], yi[16];
    #pragma unroll
    for (int k = 0; k < 16; ++k) { yr[k] = 0.f; yi[k] = 0.f; }
    #pragma unroll
    for (int j = 0; j < 16; ++j) {
        float xj = xv[j];
        #pragma unroll
        for (int k = 0; k < 16; ++k) {
            yr[k] = fmaf(xj, c_p[k * 16 + j], yr[k]);
            yi[k] = fmaf(xj, c_p[256 + k * 16 + j], yi[k]);
        }
    }

    // probs (unnormalized) dotted with Z signs; normalize by 1/||x||^2
    float d1 = 0.f, d3 = 0.f;
    #pragma unroll
    for (int k = 0; k < 16; ++k) {
        float pk = fmaf(yr[k], yr[k], yi[k] * yi[k]);
        d1 += ((k >> 2) & 1) ? -pk : pk;   // z_signs(1,4): bit mask 4
        d3 += (k & 1) ? -pk : pk;          // z_signs(3,4): bit mask 1
    }
    float inv = 1.0f / n2;
    float e1 = d1 * inv;
    float e3 = d3 * inv;

    // layer 2: RY angle embedding (unit-norm by construction)
    float s0, c0, s1, c1;
    __sincosf(0.5f * e1, &s0, &c0);
    __sincosf(0.5f * e3, &s1, &c1);
    float ps[4] = {c0 * c1, c0 * s1, s0 * c1, s0 * s1};

    float zr[4] = {0.f, 0.f, 0.f, 0.f}, zi[4] = {0.f, 0.f, 0.f, 0.f};
    #pragma unroll
    for (int j = 0; j < 4; ++j) {
        float pj = ps[j];
        #pragma unroll
        for (int k = 0; k < 4; ++k) {
            zr[k] = fmaf(pj, c_p[512 + k * 4 + j], zr[k]);
            zi[k] = fmaf(pj, c_p[528 + k * 4 + j], zi[k]);
        }
    }
    float e = 0.f;
    #pragma unroll
    for (int k = 0; k < 4; ++k) {
        float pk = fmaf(zr[k], zr[k], zi[k] * zi[k]);
        e += (k & 1) ? -pk : pk;           // z_signs(1,2): bit mask 1
    }

    out[i] = make_float2(fmaf(e, c_p[544], c_p[546]),
                         fmaf(e, c_p[545], c_p[547]));
}

// ---------------------------------------------------------------------------
extern "C" void kernel_launch(void* const* d_in, const int* in_sizes, int n_in,
                              void* d_out, int out_size) {
    const float* x  = (const float*)d_in[0];
    const float* f1 = (const float*)d_in[1];
    const float* p1 = (const float*)d_in[2];
    const float* f2 = (const float*)d_in[3];
    const float* p2 = (const float*)d_in[4];
    const float* W  = (const float*)d_in[5];
    const float* b  = (const float*)d_in[6];

    int B = in_sizes[0] / 16;

    setup_kernel<<<1, 256>>>(f1, p1, f2, p2, W, b);

    void* src = nullptr;
    cudaGetSymbolAddress(&src, g_params);
    cudaMemcpyToSymbolAsync(c_p, src, 548 * sizeof(float), 0,
                            cudaMemcpyDeviceToDevice, 0);

    int threads = 256;
    int blocks = (B + threads - 1) / threads;
    qfcn_main<<<blocks, threads>>>((const float4*)x, (float2*)d_out, B);
}

// round 13
// speedup vs baseline: 1.3601x; 1.3601x over previous
#include <cuda_runtime.h>
#include <cuda_bf16.h>
#include <cstdint>

typedef unsigned long long u64;

// Parameter block (548 floats):
//  [0   .. 512)  coef pairs, float2[(j*16+k)] = ( A[k][j], B[k][j] )
//                A = Re(U1^H Z1 U1), B = Re(U1^H Z3 U1)  (real symmetric)
//  [512 .. 544)  U2 pairs,  float2[(j*4+k)]  = ( Re U2[k][j], Im U2[k][j] )
//  [544 .. 548)  W0, W1, b0, b1
__device__ float g_params[548];

// ---------------- packed f32x2 helpers ----------------
__device__ __forceinline__ u64 fma2(u64 a, u64 b, u64 c) {
    u64 d;
    asm("fma.rn.f32x2 %0, %1, %2, %3;" : "=l"(d) : "l"(a), "l"(b), "l"(c));
    return d;
}
__device__ __forceinline__ u64 pack2(float lo, float hi) {
    u64 d; asm("mov.b64 %0, {%1, %2};" : "=l"(d) : "f"(lo), "f"(hi)); return d;
}
__device__ __forceinline__ void unpack2(u64 v, float& lo, float& hi) {
    asm("mov.b64 {%0, %1}, %2;" : "=f"(lo), "=f"(hi) : "l"(v));
}

// ---------------------------------------------------------------------------
// Setup kernel: build U1 (16x16), fold into quadratic forms A,B; build U2.
// ---------------------------------------------------------------------------
__global__ void setup_kernel(const float* __restrict__ f1,
                             const float* __restrict__ p1,
                             const float* __restrict__ f2,
                             const float* __restrict__ p2,
                             const float* __restrict__ W,
                             const float* __restrict__ b) {
    __shared__ float2 U[256];
    __shared__ float2 T[256];
    const float TWO_PI = 6.2831853071795864769f;

    const int t = threadIdx.x;
    const int m = t >> 4;     // row
    const int j = t & 15;     // col

    // ---- 1. U = Q (QFT, 4 qubits) ----
    {
        int mj = (m * j) & 15;
        float s, c;
        sincosf(TWO_PI * (float)mj * (1.0f / 16.0f), &s, &c);
        U[t] = make_float2(c * 0.25f, s * 0.25f);
    }
    __syncthreads();

    // ---- 2. RZ(f1[i]) diagonal phases ----
    {
        float ph = 0.0f;
        #pragma unroll
        for (int i = 0; i < 4; ++i) {
            float half = 0.5f * f1[i];
            ph += ((m >> (3 - i)) & 1) ? half : -half;
        }
        float s, c; sincosf(ph, &s, &c);
        float2 v = U[t];
        U[t] = make_float2(v.x * c - v.y * s, v.x * s + v.y * c);
    }
    __syncthreads();

    // ---- 3. U = Qdag @ U ----
    {
        float2 acc = make_float2(0.f, 0.f);
        for (int k = 0; k < 16; ++k) {
            int km = (k * m) & 15;
            float s, c;
            sincosf(-TWO_PI * (float)km * (1.0f / 16.0f), &s, &c);
            float2 v = U[k * 16 + j];
            acc.x += c * v.x - s * v.y;
            acc.y += c * v.y + s * v.x;
        }
        T[t] = make_float2(acc.x * 0.25f, acc.y * 0.25f);
    }
    __syncthreads();
    U[t] = T[t];
    __syncthreads();

    auto crz = [&](float theta, int cm, int tm) {
        if (m & cm) {
            float ph = (m & tm) ? 0.5f * theta : -0.5f * theta;
            float s, c; sincosf(ph, &s, &c);
            float2 v = U[t];
            U[t] = make_float2(v.x * c - v.y * s, v.x * s + v.y * c);
        }
        __syncthreads();
    };
    auto xgate = [&](int fm) {
        float2 v = U[(m ^ fm) * 16 + j];
        __syncthreads();
        U[t] = v;
        __syncthreads();
    };
    auto crx = [&](float theta, int cm, int tm) {
        float s, c; sincosf(0.5f * theta, &s, &c);
        float2 vs = U[t];
        float2 vp = U[(m ^ tm) * 16 + j];
        __syncthreads();
        if (m & cm) {
            U[t] = make_float2(c * vs.x + s * vp.y, c * vs.y - s * vp.x);
        }
        __syncthreads();
    };

    crz(p1[0], 8, 4); xgate(8); crx(p1[1], 8, 4); xgate(8);
    crz(p1[0], 2, 1); xgate(2); crx(p1[1], 2, 1); xgate(2);

    // ---- Fold into real quadratic forms:
    // A[k][j] = sum_m z1_m (Ur[m][k]Ur[m][j] + Ui[m][k]Ui[m][j]), z1 sign mask 4
    // B[k][j] = same with z3 sign mask 1
    // Thread t = (jj, kk) writes packed pair at index jj*16+kk = t.
    {
        int jj = t >> 4, kk = t & 15;
        float m1 = 0.f, m3 = 0.f;
        #pragma unroll
        for (int mm = 0; mm < 16; ++mm) {
            float2 uk = U[mm * 16 + kk];
            float2 uj = U[mm * 16 + jj];
            float r = uk.x * uj.x + uk.y * uj.y;
            m1 += (mm & 4) ? -r : r;
            m3 += (mm & 1) ? -r : r;
        }
        ((float2*)g_params)[t] = make_float2(m1, m3);
    }

    // ---- U2 (4x4), serial on thread 0 ----
    if (t == 0) {
        float2 V[16], Tm[16];
        for (int mm = 0; mm < 4; ++mm)
            for (int jj = 0; jj < 4; ++jj) {
                int mj = (mm * jj) & 3;
                float s, c; sincosf(TWO_PI * (float)mj * 0.25f, &s, &c);
                V[mm * 4 + jj] = make_float2(c * 0.5f, s * 0.5f);
            }
        for (int mm = 0; mm < 4; ++mm) {
            float ph = ((mm & 2) ? 0.5f : -0.5f) * f2[0]
                     + ((mm & 1) ? 0.5f : -0.5f) * f2[1];
            float s, c; sincosf(ph, &s, &c);
            for (int jj = 0; jj < 4; ++jj) {
                float2 v = V[mm * 4 + jj];
                V[mm * 4 + jj] = make_float2(v.x * c - v.y * s, v.x * s + v.y * c);
            }
        }
        for (int mm = 0; mm < 4; ++mm)
            for (int jj = 0; jj < 4; ++jj) {
                float2 acc = make_float2(0.f, 0.f);
                for (int k = 0; k < 4; ++k) {
                    int km = (k * mm) & 3;
                    float s, c; sincosf(-TWO_PI * (float)km * 0.25f, &s, &c);
                    float2 v = V[k * 4 + jj];
                    acc.x += c * v.x - s * v.y;
                    acc.y += c * v.y + s * v.x;
                }
                Tm[mm * 4 + jj] = make_float2(acc.x * 0.5f, acc.y * 0.5f);
            }
        for (int q = 0; q < 16; ++q) V[q] = Tm[q];
        // CRZ(p2[0]) wire0
        for (int mm = 0; mm < 4; ++mm) {
            if (mm & 2) {
                float ph = (mm & 1) ? 0.5f * p2[0] : -0.5f * p2[0];
                float s, c; sincosf(ph, &s, &c);
                for (int jj = 0; jj < 4; ++jj) {
                    float2 v = V[mm * 4 + jj];
                    V[mm * 4 + jj] = make_float2(v.x * c - v.y * s, v.x * s + v.y * c);
                }
            }
        }
        // X wire0
        for (int jj = 0; jj < 4; ++jj) {
            float2 tmp = V[0 * 4 + jj]; V[0 * 4 + jj] = V[2 * 4 + jj]; V[2 * 4 + jj] = tmp;
            tmp = V[1 * 4 + jj]; V[1 * 4 + jj] = V[3 * 4 + jj]; V[3 * 4 + jj] = tmp;
        }
        // CRX(p2[1]) wire0
        {
            float s, c; sincosf(0.5f * p2[1], &s, &c);
            for (int jj = 0; jj < 4; ++jj) {
                float2 r2 = V[2 * 4 + jj], r3 = V[3 * 4 + jj];
                V[2 * 4 + jj] = make_float2(c * r2.x + s * r3.y, c * r2.y - s * r3.x);
                V[3 * 4 + jj] = make_float2(c * r3.x + s * r2.y, c * r3.y - s * r2.x);
            }
        }
        // X wire0
        for (int jj = 0; jj < 4; ++jj) {
            float2 tmp = V[0 * 4 + jj]; V[0 * 4 + jj] = V[2 * 4 + jj]; V[2 * 4 + jj] = tmp;
            tmp = V[1 * 4 + jj]; V[1 * 4 + jj] = V[3 * 4 + jj]; V[3 * 4 + jj] = tmp;
        }
        // packed (re, im) at index jj*4+kk
        for (int jj = 0; jj < 4; ++jj)
            for (int kk = 0; kk < 4; ++kk)
                ((float2*)g_params)[256 + jj * 4 + kk] =
                    make_float2(V[kk * 4 + jj].x, V[kk * 4 + jj].y);
        g_params[544] = W[0];
        g_params[545] = W[1];
        g_params[546] = b[0];
        g_params[547] = b[1];
    }
}

// ---------------------------------------------------------------------------
// Main kernel: one element/thread. Packed f32x2 FFMA on (A,B) quadratic forms,
// coefficients broadcast from shared memory via 16B LDS.
// ---------------------------------------------------------------------------
__global__ void __launch_bounds__(256)
qfcn_main(const float4* __restrict__ x, float2* __restrict__ out, int B) {
    __shared__ __align__(16) u64 sC[256];   // (A,B) pairs, idx j*16+k
    __shared__ __align__(16) u64 sU2[16];   // (ReU2, ImU2) pairs, idx j*4+k
    __shared__ float sWb[4];

    const int tid = threadIdx.x;
    const u64* gp = (const u64*)g_params;
    sC[tid] = gp[tid];
    if (tid < 16) sU2[tid] = gp[256 + tid];
    if (tid < 4)  sWb[tid] = g_params[544 + tid];
    __syncthreads();

    const int i = blockIdx.x * blockDim.x + tid;
    if (i >= B) return;

    float4 a0 = x[4 * i + 0];
    float4 a1 = x[4 * i + 1];
    float4 a2 = x[4 * i + 2];
    float4 a3 = x[4 * i + 3];
    float xv[16] = {a0.x, a0.y, a0.z, a0.w,
                    a1.x, a1.y, a1.z, a1.w,
                    a2.x, a2.y, a2.z, a2.w,
                    a3.x, a3.y, a3.z, a3.w};

    float n2 = 0.f;
    #pragma unroll
    for (int j = 0; j < 16; ++j) n2 = fmaf(xv[j], xv[j], n2);

    const uint32_t base = (uint32_t)__cvta_generic_to_shared(sC);

    u64 z[16];
    #pragma unroll
    for (int k = 0; k < 16; ++k) z[k] = 0ULL;

    #pragma unroll
    for (int j = 0; j < 16; ++j) {
        u64 xj2 = pack2(xv[j], xv[j]);
        #pragma unroll
        for (int k = 0; k < 16; k += 2) {
            u64 c0, c1;
            asm("ld.shared.v2.u64 {%0, %1}, [%2];"
                : "=l"(c0), "=l"(c1)
                : "r"(base + (unsigned)((j * 16 + k) * 8)));
            z[k]     = fma2(xj2, c0, z[k]);
            z[k + 1] = fma2(xj2, c1, z[k + 1]);
        }
    }

    // (d1, d3) = (x . z1, x . z3), packed
    u64 dd = 0ULL;
    #pragma unroll
    for (int k = 0; k < 16; ++k) dd = fma2(pack2(xv[k], xv[k]), z[k], dd);

    float d1, d3; unpack2(dd, d1, d3);
    float inv = 1.0f / n2;
    float e1 = d1 * inv;
    float e3 = d3 * inv;

    // layer 2
    float s0, c0f, s1, c1f;
    __sincosf(0.5f * e1, &s0, &c0f);
    __sincosf(0.5f * e3, &s1, &c1f);
    float ps[4] = {c0f * c1f, c0f * s1, s0 * c1f, s0 * s1};

    u64 w[4] = {0ULL, 0ULL, 0ULL, 0ULL};
    #pragma unroll
    for (int j = 0; j < 4; ++j) {
        u64 pj2 = pack2(ps[j], ps[j]);
        #pragma unroll
        for (int k = 0; k < 4; ++k)
            w[k] = fma2(pj2, sU2[j * 4 + k], w[k]);
    }
    float e = 0.f;
    #pragma unroll
    for (int k = 0; k < 4; ++k) {
        float wr, wi; unpack2(w[k], wr, wi);
        float pk = fmaf(wr, wr, wi * wi);
        e += (k & 1) ? -pk : pk;
    }

    out[i] = make_float2(fmaf(e, sWb[0], sWb[2]),
                         fmaf(e, sWb[1], sWb[3]));
}

// ---------------------------------------------------------------------------
extern "C" void kernel_launch(void* const* d_in, const int* in_sizes, int n_in,
                              void* d_out, int out_size) {
    const float* x  = (const float*)d_in[0];
    const float* f1 = (const float*)d_in[1];
    const float* p1 = (const float*)d_in[2];
    const float* f2 = (const float*)d_in[3];
    const float* p2 = (const float*)d_in[4];
    const float* W  = (const float*)d_in[5];
    const float* b  = (const float*)d_in[6];

    int B = in_sizes[0] / 16;

    setup_kernel<<<1, 256>>>(f1, p1, f2, p2, W, b);

    int threads = 256;
    int blocks = (B + threads - 1) / threads;
    qfcn_main<<<blocks, threads>>>((const float4*)x, (float2*)d_out, B);
}

// round 14
// speedup vs baseline: 1.8186x; 1.3372x over previous
#include <cuda_runtime.h>
#include <cuda_bf16.h>
#include <cstdint>

typedef unsigned long long u64;

// Parameter block, viewed as u64[162] (= float[324]):
//  u64 [0 .. 144)   coefficient stream: 36 iterations x 4 u64:
//                   { cPA, cPB, cQA, cQB } for pair (a,b), a<=b, a-major order.
//                   cPA = (sc*A[2a][2b],   sc*A[2a+1][2b+1])   sc = (a<b ? 2 : 1)
//                   cQA = a<b ? (2A[2a][2b+1], 2A[2a+1][2b]) : (A[2a][2a+1], A[2a][2a+1])
//                   cPB/cQB identical with B.
//                   A = Re(U1^H Z1 U1), B = Re(U1^H Z3 U1)  (real symmetric)
//  u64 [144 .. 160) U2 pairs: float2(Re U2[k][j], Im U2[k][j]) at idx 144 + j*4 + k
//  u64 [160 .. 162) floats W0, W1, b0, b1
__device__ __align__(16) float g_params[328];

// ---------------- packed f32x2 helpers ----------------
__device__ __forceinline__ u64 fma2(u64 a, u64 b, u64 c) {
    u64 d;
    asm("fma.rn.f32x2 %0, %1, %2, %3;" : "=l"(d) : "l"(a), "l"(b), "l"(c));
    return d;
}
__device__ __forceinline__ u64 mul2(u64 a, u64 b) {
    u64 d;
    asm("mul.rn.f32x2 %0, %1, %2;" : "=l"(d) : "l"(a), "l"(b));
    return d;
}
__device__ __forceinline__ u64 add2(u64 a, u64 b) {
    u64 d;
    asm("add.rn.f32x2 %0, %1, %2;" : "=l"(d) : "l"(a), "l"(b));
    return d;
}
__device__ __forceinline__ u64 pack2(float lo, float hi) {
    u64 d; asm("mov.b64 %0, {%1, %2};" : "=l"(d) : "f"(lo), "f"(hi)); return d;
}
__device__ __forceinline__ void unpack2(u64 v, float& lo, float& hi) {
    asm("mov.b64 {%0, %1}, %2;" : "=f"(lo), "=f"(hi) : "l"(v));
}

// ---------------------------------------------------------------------------
// Setup kernel: builds U1 (16x16, all 256 threads) and U2 (4x4, threads 0-15
// in parallel, gate phases aligned), then folds U1 into the packed symmetric
// coefficient stream.
// ---------------------------------------------------------------------------
__global__ void setup_kernel(const float* __restrict__ f1,
                             const float* __restrict__ p1,
                             const float* __restrict__ f2,
                             const float* __restrict__ p2,
                             const float* __restrict__ W,
                             const float* __restrict__ b) {
    __shared__ float2 U[256];
    __shared__ float2 T[256];
    __shared__ float2 V[16];
    __shared__ float2 Tv[16];
    const float TWO_PI = 6.2831853071795864769f;

    const int t = threadIdx.x;
    const int m = t >> 4, j = t & 15;       // U1 coords
    const bool hv = (t < 16);
    const int m2 = t >> 2, j2 = t & 3;      // U2 coords (valid for t<16)

    // ---- phase 1: QFT matrices ----
    {
        int mj = (m * j) & 15;
        float s, c;
        sincosf(TWO_PI * (float)mj * (1.0f / 16.0f), &s, &c);
        U[t] = make_float2(c * 0.25f, s * 0.25f);
        if (hv) {
            int mj2 = (m2 * j2) & 3;
            float s2, c2; sincosf(TWO_PI * (float)mj2 * 0.25f, &s2, &c2);
            V[t] = make_float2(c2 * 0.5f, s2 * 0.5f);
        }
    }
    __syncthreads();

    // ---- phase 2: RZ diagonal phases ----
    {
        float ph = 0.0f;
        #pragma unroll
        for (int i = 0; i < 4; ++i) {
            float half = 0.5f * f1[i];
            ph += ((m >> (3 - i)) & 1) ? half : -half;
        }
        float s, c; sincosf(ph, &s, &c);
        float2 v = U[t];
        U[t] = make_float2(v.x * c - v.y * s, v.x * s + v.y * c);
        if (hv) {
            float ph2 = ((m2 & 2) ? 0.5f : -0.5f) * f2[0]
                      + ((m2 & 1) ? 0.5f : -0.5f) * f2[1];
            float s2, c2; sincosf(ph2, &s2, &c2);
            float2 w = V[t];
            V[t] = make_float2(w.x * c2 - w.y * s2, w.x * s2 + w.y * c2);
        }
    }
    __syncthreads();

    // ---- phase 3: left-multiply by Qdag ----
    {
        float2 acc = make_float2(0.f, 0.f);
        for (int k = 0; k < 16; ++k) {
            int km = (k * m) & 15;
            float s, c;
            sincosf(-TWO_PI * (float)km * (1.0f / 16.0f), &s, &c);
            float2 v = U[k * 16 + j];
            acc.x += c * v.x - s * v.y;
            acc.y += c * v.y + s * v.x;
        }
        T[t] = make_float2(acc.x * 0.25f, acc.y * 0.25f);
        if (hv) {
            float2 acc2 = make_float2(0.f, 0.f);
            for (int k = 0; k < 4; ++k) {
                int km = (k * m2) & 3;
                float s, c; sincosf(-TWO_PI * (float)km * 0.25f, &s, &c);
                float2 v = V[k * 4 + j2];
                acc2.x += c * v.x - s * v.y;
                acc2.y += c * v.y + s * v.x;
            }
            Tv[t] = make_float2(acc2.x * 0.5f, acc2.y * 0.5f);
        }
    }
    __syncthreads();
    U[t] = T[t];
    if (hv) V[t] = Tv[t];
    __syncthreads();

    // Unified gate helpers; U2 ops ride along on the first 4 gate slots.
    auto crz_both = [&](float th, int cm, int tm, bool dov, float thv) {
        if (m & cm) {
            float ph = (m & tm) ? 0.5f * th : -0.5f * th;
            float s, c; sincosf(ph, &s, &c);
            float2 v = U[t];
            U[t] = make_float2(v.x * c - v.y * s, v.x * s + v.y * c);
        }
        if (dov && hv && (m2 & 2)) {
            float ph = (m2 & 1) ? 0.5f * thv : -0.5f * thv;
            float s, c; sincosf(ph, &s, &c);
            float2 v = V[t];
            V[t] = make_float2(v.x * c - v.y * s, v.x * s + v.y * c);
        }
        __syncthreads();
    };
    auto x_both = [&](int fm, bool dov) {
        float2 a = U[(m ^ fm) * 16 + j];
        float2 bv;
        if (dov && hv) bv = V[(m2 ^ 2) * 4 + j2];
        __syncthreads();
        U[t] = a;
        if (dov && hv) V[t] = bv;
        __syncthreads();
    };
    auto crx_both = [&](float th, int cm, int tm, bool dov, float thv) {
        float s, c; sincosf(0.5f * th, &s, &c);
        float2 vs = U[t];
        float2 vp = U[(m ^ tm) * 16 + j];
        float sv, cv; float2 ws, wp;
        if (dov && hv) {
            sincosf(0.5f * thv, &sv, &cv);
            ws = V[t];
            wp = V[(m2 ^ 1) * 4 + j2];
        }
        __syncthreads();
        if (m & cm)
            U[t] = make_float2(c * vs.x + s * vp.y, c * vs.y - s * vp.x);
        if (dov && hv && (m2 & 2))
            V[t] = make_float2(cv * ws.x + sv * wp.y, cv * ws.y - sv * wp.x);
        __syncthreads();
    };

    crz_both(p1[0], 8, 4, true,  p2[0]);
    x_both  (8,          true);
    crx_both(p1[1], 8, 4, true,  p2[1]);
    x_both  (8,          true);
    crz_both(p1[0], 2, 1, false, 0.f);
    x_both  (2,          false);
    crx_both(p1[1], 2, 1, false, 0.f);
    x_both  (2,          false);

    // ---- fold U1 into the packed symmetric coefficient stream (288 floats) ----
    for (int t2 = t; t2 < 288; t2 += 256) {
        int it = t2 >> 3, slot = t2 & 7;
        // recover (a, b) for iteration it (a-major, b = a..7)
        int a = 0, rem = it;
        while (rem >= 8 - a) { rem -= 8 - a; ++a; }
        int bq = a + rem;
        bool isP = (slot < 4);
        bool isB = ((slot >> 1) & 1) != 0;
        int lane = slot & 1;
        int jj, kk; float scale;
        if (isP) {
            jj = 2 * a + lane; kk = 2 * bq + lane;
            scale = (a < bq) ? 2.f : 1.f;
        } else if (a < bq) {
            jj = 2 * a + lane; kk = 2 * bq + (1 - lane);
            scale = 2.f;
        } else {
            jj = 2 * a; kk = 2 * a + 1;
            scale = 1.f;
        }
        float sum = 0.f;
        #pragma unroll
        for (int mm = 0; mm < 16; ++mm) {
            float2 uk = U[mm * 16 + kk];
            float2 uj = U[mm * 16 + jj];
            float r = uk.x * uj.x + uk.y * uj.y;
            int neg = isB ? (mm & 1) : (mm & 4);
            sum += neg ? -r : r;
        }
        g_params[t2] = scale * sum;   // float index == t2 by construction
    }

    // ---- U2 pairs + head params ----
    if (hv) {
        // t = jj*4 + kk; store (Re U2[kk][jj], Im U2[kk][jj])
        int jj = t >> 2, kk = t & 3;
        ((float2*)g_params)[144 + t] = make_float2(V[kk * 4 + jj].x,
                                                   V[kk * 4 + jj].y);
    }
    if (t == 0) {
        g_params[320] = W[0];
        g_params[321] = W[1];
        g_params[322] = b[0];
        g_params[323] = b[1];
    }
}

// ---------------------------------------------------------------------------
// Main kernel: one element/thread. Symmetric quadratic forms via packed
// f32x2: 72 LDS.128 + ~230 FMA-pipe ops per element.
// ---------------------------------------------------------------------------
__global__ void __launch_bounds__(256)
qfcn_main(const ulonglong2* __restrict__ x, float2* __restrict__ out, int B) {
    __shared__ __align__(16) u64 sP[162];

    const int tid = threadIdx.x;
    if (tid < 162) sP[tid] = ((const u64*)g_params)[tid];
    __syncthreads();

    const int i = blockIdx.x * blockDim.x + tid;
    if (i >= B) return;

    ulonglong2 q0 = x[4 * i + 0];
    ulonglong2 q1 = x[4 * i + 1];
    ulonglong2 q2 = x[4 * i + 2];
    ulonglong2 q3 = x[4 * i + 3];
    u64 xp[8] = {q0.x, q0.y, q1.x, q1.y, q2.x, q2.y, q3.x, q3.y};

    // norm^2 (packed)
    u64 nn = 0ULL;
    #pragma unroll
    for (int a = 0; a < 8; ++a) nn = fma2(xp[a], xp[a], nn);
    float nlo, nhi; unpack2(nn, nlo, nhi);
    float n2 = nlo + nhi;

    // swapped pairs
    u64 xs[8];
    #pragma unroll
    for (int a = 0; a < 8; ++a) {
        float lo, hi; unpack2(xp[a], lo, hi);
        xs[a] = pack2(hi, lo);
    }

    const uint32_t base = (uint32_t)__cvta_generic_to_shared(sP);

    u64 aA0 = 0ULL, aA1 = 0ULL, aB0 = 0ULL, aB1 = 0ULL;
    int idx = 0;
    #pragma unroll
    for (int a = 0; a < 8; ++a) {
        #pragma unroll
        for (int bq = a; bq < 8; ++bq) {
            u64 P = mul2(xp[a], xp[bq]);
            u64 Q = mul2(xp[a], xs[bq]);
            u64 c0, c1, c2, c3;
            asm("ld.shared.v2.u64 {%0, %1}, [%2];"
                : "=l"(c0), "=l"(c1) : "r"(base + (unsigned)(idx * 32)));
            asm("ld.shared.v2.u64 {%0, %1}, [%2];"
                : "=l"(c2), "=l"(c3) : "r"(base + (unsigned)(idx * 32 + 16)));
            aA0 = fma2(P, c0, aA0);
            aB0 = fma2(P, c1, aB0);
            aA1 = fma2(Q, c2, aA1);
            aB1 = fma2(Q, c3, aB1);
            ++idx;
        }
    }

    u64 dA = add2(aA0, aA1);
    u64 dB = add2(aB0, aB1);
    float alo, ahi, blo, bhi;
    unpack2(dA, alo, ahi);
    unpack2(dB, blo, bhi);
    float inv = 1.0f / n2;
    float e1 = (alo + ahi) * inv;
    float e3 = (blo + bhi) * inv;

    // ---- layer 2 ----
    float s0, c0f, s1, c1f;
    __sincosf(0.5f * e1, &s0, &c0f);
    __sincosf(0.5f * e3, &s1, &c1f);
    float ps[4] = {c0f * c1f, c0f * s1, s0 * c1f, s0 * s1};

    const u64* sU2 = sP + 144;
    u64 w[4] = {0ULL, 0ULL, 0ULL, 0ULL};
    #pragma unroll
    for (int jj = 0; jj < 4; ++jj) {
        u64 pj2 = pack2(ps[jj], ps[jj]);
        #pragma unroll
        for (int k = 0; k < 4; ++k)
            w[k] = fma2(pj2, sU2[jj * 4 + k], w[k]);
    }
    float e = 0.f;
    #pragma unroll
    for (int k = 0; k < 4; ++k) {
        float wr, wi; unpack2(w[k], wr, wi);
        float pk = fmaf(wr, wr, wi * wi);
        e += (k & 1) ? -pk : pk;
    }

    const float* sWb = (const float*)(sP + 160);
    out[i] = make_float2(fmaf(e, sWb[0], sWb[2]),
                         fmaf(e, sWb[1], sWb[3]));
}

// ---------------------------------------------------------------------------
extern "C" void kernel_launch(void* const* d_in, const int* in_sizes, int n_in,
                              void* d_out, int out_size) {
    const float* x  = (const float*)d_in[0];
    const float* f1 = (const float*)d_in[1];
    const float* p1 = (const float*)d_in[2];
    const float* f2 = (const float*)d_in[3];
    const float* p2 = (const float*)d_in[4];
    const float* W  = (const float*)d_in[5];
    const float* b  = (const float*)d_in[6];

    int B = in_sizes[0] / 16;

    setup_kernel<<<1, 256>>>(f1, p1, f2, p2, W, b);

    int threads = 256;
    int blocks = (B + threads - 1) / threads;
    qfcn_main<<<blocks, threads>>>((const ulonglong2*)x, (float2*)d_out, B);
}

// round 15
// speedup vs baseline: 1.9778x; 1.0875x over previous
#include <cuda_runtime.h>
#include <cuda_bf16.h>
#include <cstdint>

typedef unsigned long long u64;

// Parameter block, viewed as u64[162] (= float[324]):
//  u64 [0 .. 144)   coefficient stream: 36 iterations x 4 u64:
//                   { cPA, cPB, cQA, cQB } for pair (a,b), a<=b, a-major order.
//  u64 [144 .. 160) U2 pairs: float2(Re U2[k][j], Im U2[k][j]) at idx 144 + j*4 + k
//  u64 [160 .. 162) floats W0, W1, b0, b1
__device__ __align__(16) float g_params[328];

// ---------------- packed f32x2 helpers ----------------
__device__ __forceinline__ u64 fma2(u64 a, u64 b, u64 c) {
    u64 d;
    asm("fma.rn.f32x2 %0, %1, %2, %3;" : "=l"(d) : "l"(a), "l"(b), "l"(c));
    return d;
}
__device__ __forceinline__ u64 mul2(u64 a, u64 b) {
    u64 d;
    asm("mul.rn.f32x2 %0, %1, %2;" : "=l"(d) : "l"(a), "l"(b));
    return d;
}
__device__ __forceinline__ u64 add2(u64 a, u64 b) {
    u64 d;
    asm("add.rn.f32x2 %0, %1, %2;" : "=l"(d) : "l"(a), "l"(b));
    return d;
}
__device__ __forceinline__ u64 pack2(float lo, float hi) {
    u64 d; asm("mov.b64 %0, {%1, %2};" : "=l"(d) : "f"(lo), "f"(hi)); return d;
}
__device__ __forceinline__ void unpack2(u64 v, float& lo, float& hi) {
    asm("mov.b64 {%0, %1}, %2;" : "=f"(lo), "=f"(hi) : "l"(v));
}

// ---------------------------------------------------------------------------
// Setup kernel (unchanged from R13): builds U1, U2 and folds into the packed
// symmetric coefficient stream.
// ---------------------------------------------------------------------------
__global__ void setup_kernel(const float* __restrict__ f1,
                             const float* __restrict__ p1,
                             const float* __restrict__ f2,
                             const float* __restrict__ p2,
                             const float* __restrict__ W,
                             const float* __restrict__ b) {
    __shared__ float2 U[256];
    __shared__ float2 T[256];
    __shared__ float2 V[16];
    __shared__ float2 Tv[16];
    const float TWO_PI = 6.2831853071795864769f;

    const int t = threadIdx.x;
    const int m = t >> 4, j = t & 15;
    const bool hv = (t < 16);
    const int m2 = t >> 2, j2 = t & 3;

    {
        int mj = (m * j) & 15;
        float s, c;
        sincosf(TWO_PI * (float)mj * (1.0f / 16.0f), &s, &c);
        U[t] = make_float2(c * 0.25f, s * 0.25f);
        if (hv) {
            int mj2 = (m2 * j2) & 3;
            float s2, c2; sincosf(TWO_PI * (float)mj2 * 0.25f, &s2, &c2);
            V[t] = make_float2(c2 * 0.5f, s2 * 0.5f);
        }
    }
    __syncthreads();

    {
        float ph = 0.0f;
        #pragma unroll
        for (int i = 0; i < 4; ++i) {
            float half = 0.5f * f1[i];
            ph += ((m >> (3 - i)) & 1) ? half : -half;
        }
        float s, c; sincosf(ph, &s, &c);
        float2 v = U[t];
        U[t] = make_float2(v.x * c - v.y * s, v.x * s + v.y * c);
        if (hv) {
            float ph2 = ((m2 & 2) ? 0.5f : -0.5f) * f2[0]
                      + ((m2 & 1) ? 0.5f : -0.5f) * f2[1];
            float s2, c2; sincosf(ph2, &s2, &c2);
            float2 w = V[t];
            V[t] = make_float2(w.x * c2 - w.y * s2, w.x * s2 + w.y * c2);
        }
    }
    __syncthreads();

    {
        float2 acc = make_float2(0.f, 0.f);
        for (int k = 0; k < 16; ++k) {
            int km = (k * m) & 15;
            float s, c;
            sincosf(-TWO_PI * (float)km * (1.0f / 16.0f), &s, &c);
            float2 v = U[k * 16 + j];
            acc.x += c * v.x - s * v.y;
            acc.y += c * v.y + s * v.x;
        }
        T[t] = make_float2(acc.x * 0.25f, acc.y * 0.25f);
        if (hv) {
            float2 acc2 = make_float2(0.f, 0.f);
            for (int k = 0; k < 4; ++k) {
                int km = (k * m2) & 3;
                float s, c; sincosf(-TWO_PI * (float)km * 0.25f, &s, &c);
                float2 v = V[k * 4 + j2];
                acc2.x += c * v.x - s * v.y;
                acc2.y += c * v.y + s * v.x;
            }
            Tv[t] = make_float2(acc2.x * 0.5f, acc2.y * 0.5f);
        }
    }
    __syncthreads();
    U[t] = T[t];
    if (hv) V[t] = Tv[t];
    __syncthreads();

    auto crz_both = [&](float th, int cm, int tm, bool dov, float thv) {
        if (m & cm) {
            float ph = (m & tm) ? 0.5f * th : -0.5f * th;
            float s, c; sincosf(ph, &s, &c);
            float2 v = U[t];
            U[t] = make_float2(v.x * c - v.y * s, v.x * s + v.y * c);
        }
        if (dov && hv && (m2 & 2)) {
            float ph = (m2 & 1) ? 0.5f * thv : -0.5f * thv;
            float s, c; sincosf(ph, &s, &c);
            float2 v = V[t];
            V[t] = make_float2(v.x * c - v.y * s, v.x * s + v.y * c);
        }
        __syncthreads();
    };
    auto x_both = [&](int fm, bool dov) {
        float2 a = U[(m ^ fm) * 16 + j];
        float2 bv;
        if (dov && hv) bv = V[(m2 ^ 2) * 4 + j2];
        __syncthreads();
        U[t] = a;
        if (dov && hv) V[t] = bv;
        __syncthreads();
    };
    auto crx_both = [&](float th, int cm, int tm, bool dov, float thv) {
        float s, c; sincosf(0.5f * th, &s, &c);
        float2 vs = U[t];
        float2 vp = U[(m ^ tm) * 16 + j];
        float sv, cv; float2 ws, wp;
        if (dov && hv) {
            sincosf(0.5f * thv, &sv, &cv);
            ws = V[t];
            wp = V[(m2 ^ 1) * 4 + j2];
        }
        __syncthreads();
        if (m & cm)
            U[t] = make_float2(c * vs.x + s * vp.y, c * vs.y - s * vp.x);
        if (dov && hv && (m2 & 2))
            V[t] = make_float2(cv * ws.x + sv * wp.y, cv * ws.y - sv * wp.x);
        __syncthreads();
    };

    crz_both(p1[0], 8, 4, true,  p2[0]);
    x_both  (8,          true);
    crx_both(p1[1], 8, 4, true,  p2[1]);
    x_both  (8,          true);
    crz_both(p1[0], 2, 1, false, 0.f);
    x_both  (2,          false);
    crx_both(p1[1], 2, 1, false, 0.f);
    x_both  (2,          false);

    for (int t2 = t; t2 < 288; t2 += 256) {
        int it = t2 >> 3, slot = t2 & 7;
        int a = 0, rem = it;
        while (rem >= 8 - a) { rem -= 8 - a; ++a; }
        int bq = a + rem;
        bool isP = (slot < 4);
        bool isB = ((slot >> 1) & 1) != 0;
        int lane = slot & 1;
        int jj, kk; float scale;
        if (isP) {
            jj = 2 * a + lane; kk = 2 * bq + lane;
            scale = (a < bq) ? 2.f : 1.f;
        } else if (a < bq) {
            jj = 2 * a + lane; kk = 2 * bq + (1 - lane);
            scale = 2.f;
        } else {
            jj = 2 * a; kk = 2 * a + 1;
            scale = 1.f;
        }
        float sum = 0.f;
        #pragma unroll
        for (int mm = 0; mm < 16; ++mm) {
            float2 uk = U[mm * 16 + kk];
            float2 uj = U[mm * 16 + jj];
            float r = uk.x * uj.x + uk.y * uj.y;
            int neg = isB ? (mm & 1) : (mm & 4);
            sum += neg ? -r : r;
        }
        g_params[t2] = scale * sum;
    }

    if (hv) {
        int jj = t >> 2, kk = t & 3;
        ((float2*)g_params)[144 + t] = make_float2(V[kk * 4 + jj].x,
                                                   V[kk * 4 + jj].y);
    }
    if (t == 0) {
        g_params[320] = W[0];
        g_params[321] = W[1];
        g_params[322] = b[0];
        g_params[323] = b[1];
    }
}

// ---------------------------------------------------------------------------
// Main kernel: TWO elements per thread — coefficient LDS amortized 2x.
// ---------------------------------------------------------------------------
__global__ void __launch_bounds__(256)
qfcn_main(const ulonglong2* __restrict__ x, float2* __restrict__ out,
          int B, int H) {
    __shared__ __align__(16) u64 sP[162];

    const int tid = threadIdx.x;
    if (tid < 162) sP[tid] = ((const u64*)g_params)[tid];
    __syncthreads();

    const int i0 = blockIdx.x * blockDim.x + tid;
    if (i0 >= H) return;
    const int i1 = i0 + H;
    const bool has1 = (i1 < B);
    const int i1c = has1 ? i1 : i0;

    ulonglong2 q;
    u64 xpA[8], xpB[8];
    q = x[4 * i0 + 0]; xpA[0] = q.x; xpA[1] = q.y;
    q = x[4 * i0 + 1]; xpA[2] = q.x; xpA[3] = q.y;
    q = x[4 * i0 + 2]; xpA[4] = q.x; xpA[5] = q.y;
    q = x[4 * i0 + 3]; xpA[6] = q.x; xpA[7] = q.y;
    q = x[4 * i1c + 0]; xpB[0] = q.x; xpB[1] = q.y;
    q = x[4 * i1c + 1]; xpB[2] = q.x; xpB[3] = q.y;
    q = x[4 * i1c + 2]; xpB[4] = q.x; xpB[5] = q.y;
    q = x[4 * i1c + 3]; xpB[6] = q.x; xpB[7] = q.y;

    // norms (packed)
    u64 nA = 0ULL, nB = 0ULL;
    #pragma unroll
    for (int a = 0; a < 8; ++a) {
        nA = fma2(xpA[a], xpA[a], nA);
        nB = fma2(xpB[a], xpB[a], nB);
    }

    // swapped pairs
    u64 xsA[8], xsB[8];
    #pragma unroll
    for (int a = 0; a < 8; ++a) {
        float lo, hi;
        unpack2(xpA[a], lo, hi); xsA[a] = pack2(hi, lo);
        unpack2(xpB[a], lo, hi); xsB[a] = pack2(hi, lo);
    }

    const uint32_t base = (uint32_t)__cvta_generic_to_shared(sP);

    u64 aA0 = 0, aA1 = 0, aB0 = 0, aB1 = 0;   // element 0: (d1,d3) P/Q parts
    u64 bA0 = 0, bA1 = 0, bB0 = 0, bB1 = 0;   // element 1
    int idx = 0;
    #pragma unroll
    for (int a = 0; a < 8; ++a) {
        #pragma unroll
        for (int bq = a; bq < 8; ++bq) {
            u64 c0, c1, c2, c3;
            asm("ld.shared.v2.u64 {%0, %1}, [%2];"
                : "=l"(c0), "=l"(c1) : "r"(base + (unsigned)(idx * 32)));
            asm("ld.shared.v2.u64 {%0, %1}, [%2];"
                : "=l"(c2), "=l"(c3) : "r"(base + (unsigned)(idx * 32 + 16)));

            u64 P0 = mul2(xpA[a], xpA[bq]);
            u64 Q0 = mul2(xpA[a], xsA[bq]);
            aA0 = fma2(P0, c0, aA0);
            aB0 = fma2(P0, c1, aB0);
            aA1 = fma2(Q0, c2, aA1);
            aB1 = fma2(Q0, c3, aB1);

            u64 P1 = mul2(xpB[a], xpB[bq]);
            u64 Q1 = mul2(xpB[a], xsB[bq]);
            bA0 = fma2(P1, c0, bA0);
            bB0 = fma2(P1, c1, bB0);
            bA1 = fma2(Q1, c2, bA1);
            bB1 = fma2(Q1, c3, bB1);
            ++idx;
        }
    }

    const u64* sU2 = sP + 144;
    const float* sWb = (const float*)(sP + 160);

    // ---- epilogue per element ----
    auto epilogue = [&](u64 dA, u64 dB, u64 nn) -> float2 {
        float alo, ahi, blo, bhi, nlo, nhi;
        unpack2(dA, alo, ahi);
        unpack2(dB, blo, bhi);
        unpack2(nn, nlo, nhi);
        float inv = 1.0f / (nlo + nhi);
        float e1 = (alo + ahi) * inv;
        float e3 = (blo + bhi) * inv;

        float s0, c0f, s1, c1f;
        __sincosf(0.5f * e1, &s0, &c0f);
        __sincosf(0.5f * e3, &s1, &c1f);
        float ps[4] = {c0f * c1f, c0f * s1, s0 * c1f, s0 * s1};

        u64 w[4] = {0ULL, 0ULL, 0ULL, 0ULL};
        #pragma unroll
        for (int jj = 0; jj < 4; ++jj) {
            u64 pj2 = pack2(ps[jj], ps[jj]);
            #pragma unroll
            for (int k = 0; k < 4; ++k)
                w[k] = fma2(pj2, sU2[jj * 4 + k], w[k]);
        }
        float e = 0.f;
        #pragma unroll
        for (int k = 0; k < 4; ++k) {
            float wr, wi; unpack2(w[k], wr, wi);
            float pk = fmaf(wr, wr, wi * wi);
            e += (k & 1) ? -pk : pk;
        }
        return make_float2(fmaf(e, sWb[0], sWb[2]),
                           fmaf(e, sWb[1], sWb[3]));
    };

    out[i0] = epilogue(add2(aA0, aA1), add2(aB0, aB1), nA);
    if (has1)
        out[i1] = epilogue(add2(bA0, bA1), add2(bB0, bB1), nB);
}

// ---------------------------------------------------------------------------
extern "C" void kernel_launch(void* const* d_in, const int* in_sizes, int n_in,
                              void* d_out, int out_size) {
    const float* x  = (const float*)d_in[0];
    const float* f1 = (const float*)d_in[1];
    const float* p1 = (const float*)d_in[2];
    const float* f2 = (const float*)d_in[3];
    const float* p2 = (const float*)d_in[4];
    const float* W  = (const float*)d_in[5];
    const float* b  = (const float*)d_in[6];

    int B = in_sizes[0] / 16;
    int H = (B + 1) / 2;

    setup_kernel<<<1, 256>>>(f1, p1, f2, p2, W, b);

    int threads = 256;
    int blocks = (H + threads - 1) / threads;
    qfcn_main<<<blocks, threads>>>((const ulonglong2*)x, (float2*)d_out, B, H);
}

// round 16
// speedup vs baseline: 1.9805x; 1.0014x over previous
#include <cuda_runtime.h>
#include <cuda_bf16.h>
#include <cstdint>

typedef unsigned long long u64;

// Parameter block, viewed as u64[162] (= float[324]):
//  u64 [0 .. 144)   coefficient stream: 36 iterations x 4 u64:
//                   { cPA, cPB, cQA, cQB } for pair (a,b), a<=b, a-major order.
//                   cQ* lanes are SWAPPED relative to R13/R14: they dot with
//                   Q' = swap(x_pair[a]) * x_pair[b].
//  u64 [144 .. 160) U2 pairs: float2(Re U2[k][j], Im U2[k][j]) at idx 144 + j*4 + k
//  u64 [160 .. 162) floats W0, W1, b0, b1
__device__ __align__(16) float g_params[328];

// ---------------- packed f32x2 helpers ----------------
__device__ __forceinline__ u64 fma2(u64 a, u64 b, u64 c) {
    u64 d;
    asm("fma.rn.f32x2 %0, %1, %2, %3;" : "=l"(d) : "l"(a), "l"(b), "l"(c));
    return d;
}
__device__ __forceinline__ u64 mul2(u64 a, u64 b) {
    u64 d;
    asm("mul.rn.f32x2 %0, %1, %2;" : "=l"(d) : "l"(a), "l"(b));
    return d;
}
__device__ __forceinline__ u64 pack2(float lo, float hi) {
    u64 d; asm("mov.b64 %0, {%1, %2};" : "=l"(d) : "f"(lo), "f"(hi)); return d;
}
__device__ __forceinline__ void unpack2(u64 v, float& lo, float& hi) {
    asm("mov.b64 {%0, %1}, %2;" : "=f"(lo), "=f"(hi) : "l"(v));
}
__device__ __forceinline__ u64 swap2(u64 v) {
    float lo, hi; unpack2(v, lo, hi); return pack2(hi, lo);
}

// ---------------------------------------------------------------------------
// Setup kernel: builds U1, U2 and folds into the packed symmetric coefficient
// stream (Q coefficients lane-swapped).
// ---------------------------------------------------------------------------
__global__ void setup_kernel(const float* __restrict__ f1,
                             const float* __restrict__ p1,
                             const float* __restrict__ f2,
                             const float* __restrict__ p2,
                             const float* __restrict__ W,
                             const float* __restrict__ b) {
    __shared__ float2 U[256];
    __shared__ float2 T[256];
    __shared__ float2 V[16];
    __shared__ float2 Tv[16];
    const float TWO_PI = 6.2831853071795864769f;

    const int t = threadIdx.x;
    const int m = t >> 4, j = t & 15;
    const bool hv = (t < 16);
    const int m2 = t >> 2, j2 = t & 3;

    {
        int mj = (m * j) & 15;
        float s, c;
        sincosf(TWO_PI * (float)mj * (1.0f / 16.0f), &s, &c);
        U[t] = make_float2(c * 0.25f, s * 0.25f);
        if (hv) {
            int mj2 = (m2 * j2) & 3;
            float s2, c2; sincosf(TWO_PI * (float)mj2 * 0.25f, &s2, &c2);
            V[t] = make_float2(c2 * 0.5f, s2 * 0.5f);
        }
    }
    __syncthreads();

    {
        float ph = 0.0f;
        #pragma unroll
        for (int i = 0; i < 4; ++i) {
            float half = 0.5f * f1[i];
            ph += ((m >> (3 - i)) & 1) ? half : -half;
        }
        float s, c; sincosf(ph, &s, &c);
        float2 v = U[t];
        U[t] = make_float2(v.x * c - v.y * s, v.x * s + v.y * c);
        if (hv) {
            float ph2 = ((m2 & 2) ? 0.5f : -0.5f) * f2[0]
                      + ((m2 & 1) ? 0.5f : -0.5f) * f2[1];
            float s2, c2; sincosf(ph2, &s2, &c2);
            float2 w = V[t];
            V[t] = make_float2(w.x * c2 - w.y * s2, w.x * s2 + w.y * c2);
        }
    }
    __syncthreads();

    {
        float2 acc = make_float2(0.f, 0.f);
        for (int k = 0; k < 16; ++k) {
            int km = (k * m) & 15;
            float s, c;
            sincosf(-TWO_PI * (float)km * (1.0f / 16.0f), &s, &c);
            float2 v = U[k * 16 + j];
            acc.x += c * v.x - s * v.y;
            acc.y += c * v.y + s * v.x;
        }
        T[t] = make_float2(acc.x * 0.25f, acc.y * 0.25f);
        if (hv) {
            float2 acc2 = make_float2(0.f, 0.f);
            for (int k = 0; k < 4; ++k) {
                int km = (k * m2) & 3;
                float s, c; sincosf(-TWO_PI * (float)km * 0.25f, &s, &c);
                float2 v = V[k * 4 + j2];
                acc2.x += c * v.x - s * v.y;
                acc2.y += c * v.y + s * v.x;
            }
            Tv[t] = make_float2(acc2.x * 0.5f, acc2.y * 0.5f);
        }
    }
    __syncthreads();
    U[t] = T[t];
    if (hv) V[t] = Tv[t];
    __syncthreads();

    auto crz_both = [&](float th, int cm, int tm, bool dov, float thv) {
        if (m & cm) {
            float ph = (m & tm) ? 0.5f * th : -0.5f * th;
            float s, c; sincosf(ph, &s, &c);
            float2 v = U[t];
            U[t] = make_float2(v.x * c - v.y * s, v.x * s + v.y * c);
        }
        if (dov && hv && (m2 & 2)) {
            float ph = (m2 & 1) ? 0.5f * thv : -0.5f * thv;
            float s, c; sincosf(ph, &s, &c);
            float2 v = V[t];
            V[t] = make_float2(v.x * c - v.y * s, v.x * s + v.y * c);
        }
        __syncthreads();
    };
    auto x_both = [&](int fm, bool dov) {
        float2 a = U[(m ^ fm) * 16 + j];
        float2 bv;
        if (dov && hv) bv = V[(m2 ^ 2) * 4 + j2];
        __syncthreads();
        U[t] = a;
        if (dov && hv) V[t] = bv;
        __syncthreads();
    };
    auto crx_both = [&](float th, int cm, int tm, bool dov, float thv) {
        float s, c; sincosf(0.5f * th, &s, &c);
        float2 vs = U[t];
        float2 vp = U[(m ^ tm) * 16 + j];
        float sv, cv; float2 ws, wp;
        if (dov && hv) {
            sincosf(0.5f * thv, &sv, &cv);
            ws = V[t];
            wp = V[(m2 ^ 1) * 4 + j2];
        }
        __syncthreads();
        if (m & cm)
            U[t] = make_float2(c * vs.x + s * vp.y, c * vs.y - s * vp.x);
        if (dov && hv && (m2 & 2))
            V[t] = make_float2(cv * ws.x + sv * wp.y, cv * ws.y - sv * wp.x);
        __syncthreads();
    };

    crz_both(p1[0], 8, 4, true,  p2[0]);
    x_both  (8,          true);
    crx_both(p1[1], 8, 4, true,  p2[1]);
    x_both  (8,          true);
    crz_both(p1[0], 2, 1, false, 0.f);
    x_both  (2,          false);
    crx_both(p1[1], 2, 1, false, 0.f);
    x_both  (2,          false);

    for (int t2 = t; t2 < 288; t2 += 256) {
        int it = t2 >> 3, slot = t2 & 7;
        int a = 0, rem = it;
        while (rem >= 8 - a) { rem -= 8 - a; ++a; }
        int bq = a + rem;
        bool isP = (slot < 4);
        bool isB = ((slot >> 1) & 1) != 0;
        int lane = slot & 1;
        int jj, kk; float scale;
        if (isP) {
            jj = 2 * a + lane; kk = 2 * bq + lane;
            scale = (a < bq) ? 2.f : 1.f;
        } else if (a < bq) {
            // Q coefficients lane-SWAPPED: lane0 pairs with x_{2a+1}x_{2b},
            // lane1 with x_{2a}x_{2b+1}  (matches Q' = swap(xpair_a) * xpair_b)
            jj = 2 * a + (1 - lane); kk = 2 * bq + lane;
            scale = 2.f;
        } else {
            jj = 2 * a; kk = 2 * a + 1;
            scale = 1.f;
        }
        float sum = 0.f;
        #pragma unroll
        for (int mm = 0; mm < 16; ++mm) {
            float2 uk = U[mm * 16 + kk];
            float2 uj = U[mm * 16 + jj];
            float r = uk.x * uj.x + uk.y * uj.y;
            int neg = isB ? (mm & 1) : (mm & 4);
            sum += neg ? -r : r;
        }
        g_params[t2] = scale * sum;
    }

    if (hv) {
        int jj = t >> 2, kk = t & 3;
        ((float2*)g_params)[144 + t] = make_float2(V[kk * 4 + jj].x,
                                                   V[kk * 4 + jj].y);
    }
    if (t == 0) {
        g_params[320] = W[0];
        g_params[321] = W[1];
        g_params[322] = b[0];
        g_params[323] = b[1];
    }
}

// ---------------------------------------------------------------------------
// Main kernel: two elements per thread, no swapped-x arrays (swap hoisted to
// the outer loop, coefficient lanes pre-swapped at setup). 4 accumulators.
// ---------------------------------------------------------------------------
__global__ void __launch_bounds__(256, 4)
qfcn_main(const ulonglong2* __restrict__ x, float2* __restrict__ out,
          int B, int H) {
    __shared__ __align__(16) u64 sP[162];

    const int tid = threadIdx.x;
    if (tid < 162) sP[tid] = ((const u64*)g_params)[tid];
    __syncthreads();

    const int i0 = blockIdx.x * blockDim.x + tid;
    if (i0 >= H) return;
    const int i1 = i0 + H;
    const bool has1 = (i1 < B);
    const int i1c = has1 ? i1 : i0;

    ulonglong2 q;
    u64 xpA[8], xpB[8];
    q = x[4 * i0 + 0]; xpA[0] = q.x; xpA[1] = q.y;
    q = x[4 * i0 + 1]; xpA[2] = q.x; xpA[3] = q.y;
    q = x[4 * i0 + 2]; xpA[4] = q.x; xpA[5] = q.y;
    q = x[4 * i0 + 3]; xpA[6] = q.x; xpA[7] = q.y;
    q = x[4 * i1c + 0]; xpB[0] = q.x; xpB[1] = q.y;
    q = x[4 * i1c + 1]; xpB[2] = q.x; xpB[3] = q.y;
    q = x[4 * i1c + 2]; xpB[4] = q.x; xpB[5] = q.y;
    q = x[4 * i1c + 3]; xpB[6] = q.x; xpB[7] = q.y;

    // norms (packed)
    u64 nA = 0ULL, nB = 0ULL;
    #pragma unroll
    for (int a = 0; a < 8; ++a) {
        nA = fma2(xpA[a], xpA[a], nA);
        nB = fma2(xpB[a], xpB[a], nB);
    }

    const uint32_t base = (uint32_t)__cvta_generic_to_shared(sP);

    u64 accA_e0 = 0, accB_e0 = 0;   // element 0: d1/d3 accumulators
    u64 accA_e1 = 0, accB_e1 = 0;   // element 1
    int idx = 0;
    #pragma unroll
    for (int a = 0; a < 8; ++a) {
        u64 xsA = swap2(xpA[a]);
        u64 xsB = swap2(xpB[a]);
        #pragma unroll
        for (int bq = a; bq < 8; ++bq) {
            u64 c0, c1, c2, c3;
            asm("ld.shared.v2.u64 {%0, %1}, [%2];"
                : "=l"(c0), "=l"(c1) : "r"(base + (unsigned)(idx * 32)));
            asm("ld.shared.v2.u64 {%0, %1}, [%2];"
                : "=l"(c2), "=l"(c3) : "r"(base + (unsigned)(idx * 32 + 16)));

            u64 P0 = mul2(xpA[a], xpA[bq]);
            u64 Q0 = mul2(xsA,    xpA[bq]);
            accA_e0 = fma2(P0, c0, accA_e0);
            accB_e0 = fma2(P0, c1, accB_e0);
            accA_e0 = fma2(Q0, c2, accA_e0);
            accB_e0 = fma2(Q0, c3, accB_e0);

            u64 P1 = mul2(xpB[a], xpB[bq]);
            u64 Q1 = mul2(xsB,    xpB[bq]);
            accA_e1 = fma2(P1, c0, accA_e1);
            accB_e1 = fma2(P1, c1, accB_e1);
            accA_e1 = fma2(Q1, c2, accA_e1);
            accB_e1 = fma2(Q1, c3, accB_e1);
            ++idx;
        }
    }

    const u64* sU2 = sP + 144;
    const float* sWb = (const float*)(sP + 160);

    auto epilogue = [&](u64 dA, u64 dB, u64 nn) -> float2 {
        float alo, ahi, blo, bhi, nlo, nhi;
        unpack2(dA, alo, ahi);
        unpack2(dB, blo, bhi);
        unpack2(nn, nlo, nhi);
        float inv = 1.0f / (nlo + nhi);
        float e1 = (alo + ahi) * inv;
        float e3 = (blo + bhi) * inv;

        float s0, c0f, s1, c1f;
        __sincosf(0.5f * e1, &s0, &c0f);
        __sincosf(0.5f * e3, &s1, &c1f);
        float ps[4] = {c0f * c1f, c0f * s1, s0 * c1f, s0 * s1};

        u64 w[4] = {0ULL, 0ULL, 0ULL, 0ULL};
        #pragma unroll
        for (int jj = 0; jj < 4; ++jj) {
            u64 pj2 = pack2(ps[jj], ps[jj]);
            #pragma unroll
            for (int k = 0; k < 4; ++k)
                w[k] = fma2(pj2, sU2[jj * 4 + k], w[k]);
        }
        float e = 0.f;
        #pragma unroll
        for (int k = 0; k < 4; ++k) {
            float wr, wi; unpack2(w[k], wr, wi);
            float pk = fmaf(wr, wr, wi * wi);
            e += (k & 1) ? -pk : pk;
        }
        return make_float2(fmaf(e, sWb[0], sWb[2]),
                           fmaf(e, sWb[1], sWb[3]));
    };

    out[i0] = epilogue(accA_e0, accB_e0, nA);
    if (has1)
        out[i1] = epilogue(accA_e1, accB_e1, nB);
}

// ---------------------------------------------------------------------------
extern "C" void kernel_launch(void* const* d_in, const int* in_sizes, int n_in,
                              void* d_out, int out_size) {
    const float* x  = (const float*)d_in[0];
    const float* f1 = (const float*)d_in[1];
    const float* p1 = (const float*)d_in[2];
    const float* f2 = (const float*)d_in[3];
    const float* p2 = (const float*)d_in[4];
    const float* W  = (const float*)d_in[5];
    const float* b  = (const float*)d_in[6];

    int B = in_sizes[0] / 16;
    int H = (B + 1) / 2;

    setup_kernel<<<1, 256>>>(f1, p1, f2, p2, W, b);

    int threads = 256;
    int blocks = (H + threads - 1) / threads;
    qfcn_main<<<blocks, threads>>>((const ulonglong2*)x, (float2*)d_out, B, H);
}

// round 17
// speedup vs baseline: 2.3773x; 1.2003x over previous
#include <cuda_runtime.h>
#include <cuda_bf16.h>
#include <cstdint>

typedef unsigned long long u64;

// Parameter block (floats):
//  [0   .. 288)  coefficient stream: 36 iterations x 4 u64 (8 floats):
//                { cPA, cPB, cQA, cQB } for pair (a,b), a<=b, a-major order.
//                cQ* lanes pre-swapped: dot with Q' = swap(xpair_a)*xpair_b.
//  [288 .. 297)  M[3][3]: e = [1,c1,s1] M [1,c3,s3]^T  (layer-2 folded)
//  [300 .. 304)  W0, W1, b0, b1
__device__ __align__(16) float g_params[304];

// ---------------- packed f32x2 helpers ----------------
__device__ __forceinline__ u64 fma2(u64 a, u64 b, u64 c) {
    u64 d;
    asm("fma.rn.f32x2 %0, %1, %2, %3;" : "=l"(d) : "l"(a), "l"(b), "l"(c));
    return d;
}
__device__ __forceinline__ u64 mul2(u64 a, u64 b) {
    u64 d;
    asm("mul.rn.f32x2 %0, %1, %2;" : "=l"(d) : "l"(a), "l"(b));
    return d;
}
__device__ __forceinline__ u64 pack2(float lo, float hi) {
    u64 d; asm("mov.b64 %0, {%1, %2};" : "=l"(d) : "f"(lo), "f"(hi)); return d;
}
__device__ __forceinline__ void unpack2(u64 v, float& lo, float& hi) {
    asm("mov.b64 {%0, %1}, %2;" : "=f"(lo), "=f"(hi) : "l"(v));
}
__device__ __forceinline__ u64 swap2(u64 v) {
    float lo, hi; unpack2(v, lo, hi); return pack2(hi, lo);
}

// ---------------------------------------------------------------------------
// Setup kernel: builds U1 (256 thr) and U2 (thr 0-15), folds U1 into the
// packed symmetric coefficient stream and U2 into the 3x3 bilinear form M.
// All trig via __sincosf (abs err ~5e-7, tolerance is 1e-3).
// ---------------------------------------------------------------------------
__global__ void setup_kernel(const float* __restrict__ f1,
                             const float* __restrict__ p1,
                             const float* __restrict__ f2,
                             const float* __restrict__ p2,
                             const float* __restrict__ W,
                             const float* __restrict__ b) {
    __shared__ float2 U[256];
    __shared__ float2 T[256];
    __shared__ float2 V[16];
    __shared__ float2 Tv[16];
    const float TWO_PI = 6.2831853071795864769f;

    const int t = threadIdx.x;
    const int m = t >> 4, j = t & 15;
    const bool hv = (t < 16);
    const int m2 = t >> 2, j2 = t & 3;

    {
        int mj = (m * j) & 15;
        float s, c;
        __sincosf(TWO_PI * (float)mj * (1.0f / 16.0f), &s, &c);
        U[t] = make_float2(c * 0.25f, s * 0.25f);
        if (hv) {
            int mj2 = (m2 * j2) & 3;
            float s2, c2; __sincosf(TWO_PI * (float)mj2 * 0.25f, &s2, &c2);
            V[t] = make_float2(c2 * 0.5f, s2 * 0.5f);
        }
    }
    __syncthreads();

    {
        float ph = 0.0f;
        #pragma unroll
        for (int i = 0; i < 4; ++i) {
            float half = 0.5f * f1[i];
            ph += ((m >> (3 - i)) & 1) ? half : -half;
        }
        float s, c; __sincosf(ph, &s, &c);
        float2 v = U[t];
        U[t] = make_float2(v.x * c - v.y * s, v.x * s + v.y * c);
        if (hv) {
            float ph2 = ((m2 & 2) ? 0.5f : -0.5f) * f2[0]
                      + ((m2 & 1) ? 0.5f : -0.5f) * f2[1];
            float s2, c2; __sincosf(ph2, &s2, &c2);
            float2 w = V[t];
            V[t] = make_float2(w.x * c2 - w.y * s2, w.x * s2 + w.y * c2);
        }
    }
    __syncthreads();

    {
        float2 acc = make_float2(0.f, 0.f);
        for (int k = 0; k < 16; ++k) {
            int km = (k * m) & 15;
            float s, c;
            __sincosf(-TWO_PI * (float)km * (1.0f / 16.0f), &s, &c);
            float2 v = U[k * 16 + j];
            acc.x += c * v.x - s * v.y;
            acc.y += c * v.y + s * v.x;
        }
        T[t] = make_float2(acc.x * 0.25f, acc.y * 0.25f);
        if (hv) {
            float2 acc2 = make_float2(0.f, 0.f);
            for (int k = 0; k < 4; ++k) {
                int km = (k * m2) & 3;
                float s, c; __sincosf(-TWO_PI * (float)km * 0.25f, &s, &c);
                float2 v = V[k * 4 + j2];
                acc2.x += c * v.x - s * v.y;
                acc2.y += c * v.y + s * v.x;
            }
            Tv[t] = make_float2(acc2.x * 0.5f, acc2.y * 0.5f);
        }
    }
    __syncthreads();
    U[t] = T[t];
    if (hv) V[t] = Tv[t];
    __syncthreads();

    auto crz_both = [&](float th, int cm, int tm, bool dov, float thv) {
        if (m & cm) {
            float ph = (m & tm) ? 0.5f * th : -0.5f * th;
            float s, c; __sincosf(ph, &s, &c);
            float2 v = U[t];
            U[t] = make_float2(v.x * c - v.y * s, v.x * s + v.y * c);
        }
        if (dov && hv && (m2 & 2)) {
            float ph = (m2 & 1) ? 0.5f * thv : -0.5f * thv;
            float s, c; __sincosf(ph, &s, &c);
            float2 v = V[t];
            V[t] = make_float2(v.x * c - v.y * s, v.x * s + v.y * c);
        }
        __syncthreads();
    };
    auto x_both = [&](int fm, bool dov) {
        float2 a = U[(m ^ fm) * 16 + j];
        float2 bv;
        if (dov && hv) bv = V[(m2 ^ 2) * 4 + j2];
        __syncthreads();
        U[t] = a;
        if (dov && hv) V[t] = bv;
        __syncthreads();
    };
    auto crx_both = [&](float th, int cm, int tm, bool dov, float thv) {
        float s, c; __sincosf(0.5f * th, &s, &c);
        float2 vs = U[t];
        float2 vp = U[(m ^ tm) * 16 + j];
        float sv, cv; float2 ws, wp;
        if (dov && hv) {
            __sincosf(0.5f * thv, &sv, &cv);
            ws = V[t];
            wp = V[(m2 ^ 1) * 4 + j2];
        }
        __syncthreads();
        if (m & cm)
            U[t] = make_float2(c * vs.x + s * vp.y, c * vs.y - s * vp.x);
        if (dov && hv && (m2 & 2))
            V[t] = make_float2(cv * ws.x + sv * wp.y, cv * ws.y - sv * wp.x);
        __syncthreads();
    };

    crz_both(p1[0], 8, 4, true,  p2[0]);
    x_both  (8,          true);
    crx_both(p1[1], 8, 4, true,  p2[1]);
    x_both  (8,          true);
    crz_both(p1[0], 2, 1, false, 0.f);
    x_both  (2,          false);
    crx_both(p1[1], 2, 1, false, 0.f);
    x_both  (2,          false);

    // ---- fold U1 -> packed symmetric coefficient stream ----
    for (int t2 = t; t2 < 288; t2 += 256) {
        int it = t2 >> 3, slot = t2 & 7;
        int a = 0, rem = it;
        while (rem >= 8 - a) { rem -= 8 - a; ++a; }
        int bq = a + rem;
        bool isP = (slot < 4);
        bool isB = ((slot >> 1) & 1) != 0;
        int lane = slot & 1;
        int jj, kk; float scale;
        if (isP) {
            jj = 2 * a + lane; kk = 2 * bq + lane;
            scale = (a < bq) ? 2.f : 1.f;
        } else if (a < bq) {
            jj = 2 * a + (1 - lane); kk = 2 * bq + lane;
            scale = 2.f;
        } else {
            jj = 2 * a; kk = 2 * a + 1;
            scale = 1.f;
        }
        float sum = 0.f;
        #pragma unroll
        for (int mm = 0; mm < 16; ++mm) {
            float2 uk = U[mm * 16 + kk];
            float2 uj = U[mm * 16 + jj];
            float r = uk.x * uj.x + uk.y * uj.y;
            int neg = isB ? (mm & 1) : (mm & 4);
            sum += neg ? -r : r;
        }
        g_params[t2] = scale * sum;
    }

    // ---- fold U2 -> 3x3 bilinear form M ----
    if (t == 0) {
        // C[i][j] = sum_m z_m Re(conj(V[m][i]) V[m][j]),  z_m = (m&1)? -1:+1
        float C[4][4];
        for (int i = 0; i < 4; ++i)
            for (int jj = 0; jj < 4; ++jj) {
                float s = 0.f;
                for (int mm = 0; mm < 4; ++mm) {
                    float r = V[mm * 4 + i].x * V[mm * 4 + jj].x
                            + V[mm * 4 + i].y * V[mm * 4 + jj].y;
                    s += (mm & 1) ? -r : r;
                }
                C[i][jj] = s;
            }
        // basis: cos(e/2)^2=(1+c)/2, cos*sin=s/2, sin^2=(1-c)/2 on (1,c,s)
        auto basis = [](int bi, int bj, float* o) {
            if (bi == 0 && bj == 0) { o[0] = 0.5f; o[1] = 0.5f;  o[2] = 0.f;  }
            else if (bi == 1 && bj == 1) { o[0] = 0.5f; o[1] = -0.5f; o[2] = 0.f; }
            else { o[0] = 0.f; o[1] = 0.f; o[2] = 0.5f; }
        };
        float M[3][3] = {{0,0,0},{0,0,0},{0,0,0}};
        for (int i = 0; i < 4; ++i)
            for (int jj = 0; jj < 4; ++jj) {
                float b1v[3], b3v[3];
                basis(i >> 1, jj >> 1, b1v);
                basis(i & 1, jj & 1, b3v);
                float cij = C[i][jj];
                for (int a = 0; a < 3; ++a)
                    for (int bb = 0; bb < 3; ++bb)
                        M[a][bb] += cij * b1v[a] * b3v[bb];
            }
        for (int a = 0; a < 3; ++a)
            for (int bb = 0; bb < 3; ++bb)
                g_params[288 + a * 3 + bb] = M[a][bb];
        g_params[300] = W[0];
        g_params[301] = W[1];
        g_params[302] = b[0];
        g_params[303] = b[1];
    }
}

// ---------------------------------------------------------------------------
// Main kernel: two elements/thread; PDL — x loads issued before
// cudaGridDependencySynchronize(), params staged after.
// ---------------------------------------------------------------------------
__global__ void __launch_bounds__(256, 4)
qfcn_main(const ulonglong2* __restrict__ x, float2* __restrict__ out,
          int B, int H) {
    __shared__ __align__(16) u64 sP[152];

    const int tid = threadIdx.x;
    const int i0 = blockIdx.x * blockDim.x + tid;
    const int i0c = (i0 < H) ? i0 : (H - 1);
    const int i1 = i0c + H;
    const bool has1 = (i1 < B);
    const int i1c = has1 ? i1 : i0c;

    // issue x loads BEFORE waiting on the setup kernel
    ulonglong2 q;
    u64 xpA[8], xpB[8];
    q = x[4 * i0c + 0]; xpA[0] = q.x; xpA[1] = q.y;
    q = x[4 * i0c + 1]; xpA[2] = q.x; xpA[3] = q.y;
    q = x[4 * i0c + 2]; xpA[4] = q.x; xpA[5] = q.y;
    q = x[4 * i0c + 3]; xpA[6] = q.x; xpA[7] = q.y;
    q = x[4 * i1c + 0]; xpB[0] = q.x; xpB[1] = q.y;
    q = x[4 * i1c + 1]; xpB[2] = q.x; xpB[3] = q.y;
    q = x[4 * i1c + 2]; xpB[4] = q.x; xpB[5] = q.y;
    q = x[4 * i1c + 3]; xpB[6] = q.x; xpB[7] = q.y;

#if __CUDA_ARCH__ >= 900
    cudaGridDependencySynchronize();
#endif

    if (tid < 152) sP[tid] = ((const u64*)g_params)[tid];
    __syncthreads();

    // norms (packed)
    u64 nA = 0ULL, nB = 0ULL;
    #pragma unroll
    for (int a = 0; a < 8; ++a) {
        nA = fma2(xpA[a], xpA[a], nA);
        nB = fma2(xpB[a], xpB[a], nB);
    }

    const uint32_t base = (uint32_t)__cvta_generic_to_shared(sP);

    u64 accA_e0 = 0, accB_e0 = 0;
    u64 accA_e1 = 0, accB_e1 = 0;
    int idx = 0;
    #pragma unroll
    for (int a = 0; a < 8; ++a) {
        u64 xsA = swap2(xpA[a]);
        u64 xsB = swap2(xpB[a]);
        #pragma unroll
        for (int bq = a; bq < 8; ++bq) {
            u64 c0, c1, c2, c3;
            asm("ld.shared.v2.u64 {%0, %1}, [%2];"
                : "=l"(c0), "=l"(c1) : "r"(base + (unsigned)(idx * 32)));
            asm("ld.shared.v2.u64 {%0, %1}, [%2];"
                : "=l"(c2), "=l"(c3) : "r"(base + (unsigned)(idx * 32 + 16)));

            u64 P0 = mul2(xpA[a], xpA[bq]);
            u64 Q0 = mul2(xsA,    xpA[bq]);
            accA_e0 = fma2(P0, c0, accA_e0);
            accB_e0 = fma2(P0, c1, accB_e0);
            accA_e0 = fma2(Q0, c2, accA_e0);
            accB_e0 = fma2(Q0, c3, accB_e0);

            u64 P1 = mul2(xpB[a], xpB[bq]);
            u64 Q1 = mul2(xsB,    xpB[bq]);
            accA_e1 = fma2(P1, c0, accA_e1);
            accB_e1 = fma2(P1, c1, accB_e1);
            accA_e1 = fma2(Q1, c2, accA_e1);
            accB_e1 = fma2(Q1, c3, accB_e1);
            ++idx;
        }
    }

    const float* sM  = (const float*)sP + 288;
    const float* sWb = (const float*)sP + 300;

    auto epilogue = [&](u64 dA, u64 dB, u64 nn) -> float2 {
        float alo, ahi, blo, bhi, nlo, nhi;
        unpack2(dA, alo, ahi);
        unpack2(dB, blo, bhi);
        unpack2(nn, nlo, nhi);
        float inv = 1.0f / (nlo + nhi);
        float e1 = (alo + ahi) * inv;
        float e3 = (blo + bhi) * inv;

        float c1v, s1v, c3v, s3v;
        __sincosf(e1, &s1v, &c1v);
        __sincosf(e3, &s3v, &c3v);

        float g0 = fmaf(sM[2], s3v, fmaf(sM[1], c3v, sM[0]));
        float g1 = fmaf(sM[5], s3v, fmaf(sM[4], c3v, sM[3]));
        float g2 = fmaf(sM[8], s3v, fmaf(sM[7], c3v, sM[6]));
        float e  = fmaf(s1v, g2, fmaf(c1v, g1, g0));

        return make_float2(fmaf(e, sWb[0], sWb[2]),
                           fmaf(e, sWb[1], sWb[3]));
    };

    if (i0 < H) {
        out[i0] = epilogue(accA_e0, accB_e0, nA);
        if (has1)
            out[i1] = epilogue(accA_e1, accB_e1, nB);
    }
}

// ---------------------------------------------------------------------------
extern "C" void kernel_launch(void* const* d_in, const int* in_sizes, int n_in,
                              void* d_out, int out_size) {
    const float* x  = (const float*)d_in[0];
    const float* f1 = (const float*)d_in[1];
    const float* p1 = (const float*)d_in[2];
    const float* f2 = (const float*)d_in[3];
    const float* p2 = (const float*)d_in[4];
    const float* W  = (const float*)d_in[5];
    const float* b  = (const float*)d_in[6];

    int B = in_sizes[0] / 16;
    int H = (B + 1) / 2;

    setup_kernel<<<1, 256>>>(f1, p1, f2, p2, W, b);

    int threads = 256;
    int blocks = (H + threads - 1) / threads;

    // Programmatic dependent launch: overlap main's launch + x-load phase
    // with the tail of setup_kernel.
    cudaLaunchConfig_t cfg = {};
    cfg.gridDim = dim3((unsigned)blocks, 1, 1);
    cfg.blockDim = dim3((unsigned)threads, 1, 1);
    cfg.dynamicSmemBytes = 0;
    cfg.stream = 0;
    cudaLaunchAttribute attrs[1];
    attrs[0].id = cudaLaunchAttributeProgrammaticStreamSerialization;
    attrs[0].val.programmaticStreamSerializationAllowed = 1;
    cfg.attrs = attrs;
    cfg.numAttrs = 1;
    cudaLaunchKernelEx(&cfg, qfcn_main,
                       (const ulonglong2*)x, (float2*)d_out, B, H);
}